// round 15
// baseline (speedup 1.0000x reference)
#include <cuda_runtime.h>
#include <cuda_bf16.h>
#include <cuda_fp16.h>
#include <cstdint>
#include <math.h>

#define M_TOK   8192      // 4 * 2048 tokens
#define DMODEL  2048
#define NHEADS  16
#define HDIM    128
#define SEQ     2048
#define BATCH   4

// ---------------- scratch (static device allocations; no cudaMalloc) -------
__device__ __half g_qh[(size_t)M_TOK * DMODEL];
__device__ __half g_kh[(size_t)M_TOK * DMODEL];
__device__ __half g_vh[(size_t)M_TOK * DMODEL];

__device__ __half g_xh[(size_t)M_TOK * DMODEL];
__device__ __half g_chi[(size_t)M_TOK * DMODEL];
__device__ __half g_wh[(size_t)4 * DMODEL * DMODEL];

// ============================ helpers ======================================
__device__ __forceinline__ uint32_t smem_u32(const void* p) {
    uint32_t a;
    asm("{ .reg .u64 t; cvta.to.shared.u64 t, %1; cvt.u32.u64 %0, t; }"
        : "=r"(a) : "l"(p));
    return a;
}
__device__ __forceinline__ void cp_async16(uint32_t dst, const void* src) {
    asm volatile("cp.async.cg.shared.global [%0], [%1], 16;"
                 :: "r"(dst), "l"(src) : "memory");
}
__device__ __forceinline__ void cp_commit() {
    asm volatile("cp.async.commit_group;" ::: "memory");
}
__device__ __forceinline__ void cp_wait0() {
    asm volatile("cp.async.wait_group 0;" ::: "memory");
}
__device__ __forceinline__ void cp_wait1() {
    asm volatile("cp.async.wait_group 1;" ::: "memory");
}
__device__ __forceinline__ void cp_wait2() {
    asm volatile("cp.async.wait_group 2;" ::: "memory");
}
__device__ __forceinline__ float ex2(float x) {
    float y; asm("ex2.approx.f32 %0, %1;" : "=f"(y) : "f"(x)); return y;
}
__device__ __forceinline__ void mma_f16(float* d,
                                        const uint32_t* a, uint32_t b0, uint32_t b1) {
    asm volatile("mma.sync.aligned.m16n8k16.row.col.f32.f16.f16.f32 "
                 "{%0,%1,%2,%3}, {%4,%5,%6,%7}, {%8,%9}, {%0,%1,%2,%3};"
                 : "+f"(d[0]), "+f"(d[1]), "+f"(d[2]), "+f"(d[3])
                 : "r"(a[0]), "r"(a[1]), "r"(a[2]), "r"(a[3]), "r"(b0), "r"(b1));
}
#define LDMX4(r0, r1, r2, r3, addr)                                          \
    asm volatile("ldmatrix.sync.aligned.m8n8.x4.shared.b16 {%0,%1,%2,%3}, [%4];" \
                 : "=r"(r0), "=r"(r1), "=r"(r2), "=r"(r3) : "r"(addr))
#define LDMX4T(r0, r1, r2, r3, addr)                                         \
    asm volatile("ldmatrix.sync.aligned.m8n8.x4.trans.shared.b16 {%0,%1,%2,%3}, [%4];" \
                 : "=r"(r0), "=r"(r1), "=r"(r2), "=r"(r3) : "r"(addr))

__device__ __forceinline__ uint32_t pack_h2(__half a, __half b) {
    __half2 h = __halves2half2(a, b);
    return *(uint32_t*)&h;
}

// ================= fused fp32 -> fp16 convert (x and weights) ==============
// 4 float4 per thread; region boundaries are multiples of 4 (no straddle).
#define NX4 ((int)((size_t)M_TOK * DMODEL / 4))        // 4,194,304 = 2^22
#define NW4 ((int)((size_t)DMODEL * DMODEL / 4))       // 1,048,576 = 2^20

__global__ __launch_bounds__(256)
void split_all(const float4* __restrict__ x,
               const float4* __restrict__ Wq, const float4* __restrict__ Wk,
               const float4* __restrict__ Wv, const float4* __restrict__ Wo,
               __half2* __restrict__ xh, __half2* __restrict__ wh)
{
    int i0 = (blockIdx.x * 256 + threadIdx.x) * 4;
    const float4* src;
    __half2* dst;
    int off;
    if (i0 < NX4) {
        src = x; off = i0; dst = xh;
    } else {
        int r = i0 - NX4;
        int j = r >> 20;
        off = r & (NW4 - 1);
        src = (j == 0) ? Wq : (j == 1) ? Wk : (j == 2) ? Wv : Wo;
        dst = wh + (size_t)j * NW4 * 2;
    }
    float4 v[4];
#pragma unroll
    for (int u = 0; u < 4; ++u) v[u] = src[off + u];
#pragma unroll
    for (int u = 0; u < 4; ++u) {
        dst[2 * (off + u)]     = __halves2half2(__float2half_rn(v[u].x),
                                                __float2half_rn(v[u].y));
        dst[2 * (off + u) + 1] = __halves2half2(__float2half_rn(v[u].z),
                                                __float2half_rn(v[u].w));
    }
}

// === HMMA GEMM core: CTA 128x128, GBK=64, single-pass, 3-stage, 2 CTA/SM ===
// R13-proven ordering: issue load(i+2) FIRST, then wait for chunk i, sync,
// compute, sync. (Two barriers/chunk; load issue overlaps the wait.)
#define GBK 64
#define B_OFF   16384
#define STAGE   32768
#define GEMM_SMEM (3 * STAGE)        // 98304 -> 2 CTAs/SM

__device__ __forceinline__ void gemm_core(
    const __half* __restrict__ A, const __half* __restrict__ B,
    int bm0, int bn0, int K, char* dsm, float acc[2][8][4])
{
    const int tid = threadIdx.x;
    const int wid = tid >> 5;
    const int lid = tid & 31;
    const int wr = wid >> 1;             // 0..3, m-offset wr*32
    const int wc = wid & 1;              // 0..1, n-offset wc*64
    const uint32_t smbase = smem_u32(dsm);

    uint32_t aRaw[2], aXor[2], bRaw[4], bXor[4];
#pragma unroll
    for (int mt = 0; mt < 2; ++mt) {
        int row = wr * 32 + mt * 16 + (lid & 15);
        aRaw[mt] = (uint32_t)(row * 128 + ((lid & 16) ? 16 : 0));
        aXor[mt] = (uint32_t)((row << 4) & 0x70);
    }
#pragma unroll
    for (int g = 0; g < 4; ++g) {
        int nrow = wc * 64 + g * 16 + (lid & 7) + ((lid & 16) ? 8 : 0);
        bRaw[g] = (uint32_t)(nrow * 128 + ((lid & 8) ? 16 : 0));
        bXor[g] = (uint32_t)((nrow << 4) & 0x70);
    }

    // ---- hoisted loader constants (A 1024 + B 1024 16B units, 8/thread) ----
    const int rbase = tid >> 3;          // 0..31
    const int s16   = tid & 7;
    const uint32_t dstc =
        (uint32_t)((rbase * 128 + s16 * 16) ^ ((rbase << 4) & 0x70));
    const __half* sA = A + (size_t)(bm0 + rbase) * K + s16 * 8;
    const __half* sB = B + (size_t)(bn0 + rbase) * K + s16 * 8;
    const size_t rstep = (size_t)32 * K;     // 32 rows per slot

    auto load_chunk = [&](int chunk, int stage) {
        const int k0 = chunk * GBK;
        const uint32_t db = smbase + stage * STAGE + dstc;
#pragma unroll
        for (int it = 0; it < 4; ++it) {
            cp_async16(db + it * 4096,         sA + it * rstep + k0);
            cp_async16(db + B_OFF + it * 4096, sB + it * rstep + k0);
        }
        cp_commit();
    };

    const int nchunk = K / GBK;          // 32
    load_chunk(0, 0);
    load_chunk(1, 1);

    for (int i = 0; i < nchunk; ++i) {
        const int st = i % 3;
        if (i + 2 < nchunk) {
            load_chunk(i + 2, (i + 2) % 3);
            cp_wait2();                  // chunk i arrived (i+1, i+2 in flight)
        } else if (i + 1 < nchunk) {
            cp_wait1();
        } else {
            cp_wait0();
        }
        __syncthreads();

        const uint32_t sb = smbase + st * STAGE;

#pragma unroll
        for (int ks = 0; ks < 4; ++ks) {
            const uint32_t kd = ks * 32;
            uint32_t ah[2][4], bfr[8][2];
#pragma unroll
            for (int mt = 0; mt < 2; ++mt)
                LDMX4(ah[mt][0], ah[mt][1], ah[mt][2], ah[mt][3],
                      sb + ((aRaw[mt] + kd) ^ aXor[mt]));
#pragma unroll
            for (int g = 0; g < 4; ++g)
                LDMX4(bfr[2 * g][0], bfr[2 * g][1], bfr[2 * g + 1][0], bfr[2 * g + 1][1],
                      sb + B_OFF + ((bRaw[g] + kd) ^ bXor[g]));
#pragma unroll
            for (int mt = 0; mt < 2; ++mt)
#pragma unroll
                for (int nt = 0; nt < 8; ++nt)
                    mma_f16(acc[mt][nt], ah[mt], bfr[nt][0], bfr[nt][1]);
        }
        __syncthreads();   // stage st must be drained before iter i+1 reloads it
    }
}

// ---- fused QKV projection: B rows = stacked [Wq; Wk; Wv], single pass ----
__global__ __launch_bounds__(256, 2)
void gemm_qkv(const __half* __restrict__ Xh, const __half* __restrict__ W,
              __half* __restrict__ Qh, __half* __restrict__ Kh,
              __half* __restrict__ Vh, float qscale)
{
    extern __shared__ __align__(1024) char dsm[];
    const int bm0 = blockIdx.y * 128;
    const int bn0 = blockIdx.x * 128;    // 0..6016
    const int j = bn0 >> 11;             // 0=Q 1=K 2=V

    float acc[2][8][4];
#pragma unroll
    for (int a = 0; a < 2; ++a)
#pragma unroll
        for (int b = 0; b < 8; ++b)
#pragma unroll
            for (int c = 0; c < 4; ++c) acc[a][b][c] = 0.0f;

    gemm_core(Xh, W, bm0, bn0, DMODEL, dsm, acc);

    const int ncol0 = bn0 & 2047;
    __half* dst = (j == 0) ? Qh : (j == 1) ? Kh : Vh;
    const float sc = (j == 0) ? qscale : 1.0f;
    const int wid = (int)threadIdx.x >> 5;
    const int lid = (int)threadIdx.x & 31;
    const int wr = wid >> 1, wc = wid & 1;

#pragma unroll
    for (int mt = 0; mt < 2; ++mt) {
        int row0 = bm0 + wr * 32 + mt * 16 + (lid >> 2);
#pragma unroll
        for (int nt = 0; nt < 8; ++nt) {
            int col = ncol0 + wc * 64 + nt * 8 + (lid & 3) * 2;
            __half h0 = __float2half_rn(acc[mt][nt][0] * sc);
            __half h1 = __float2half_rn(acc[mt][nt][1] * sc);
            __half h2 = __float2half_rn(acc[mt][nt][2] * sc);
            __half h3 = __float2half_rn(acc[mt][nt][3] * sc);
            *(uint32_t*)(dst + (size_t)row0 * DMODEL + col)       = pack_h2(h0, h1);
            *(uint32_t*)(dst + (size_t)(row0 + 8) * DMODEL + col) = pack_h2(h2, h3);
        }
    }
}

// ---- output projection: single-pass fp16 ctx, fp32 out + bias ----
__global__ __launch_bounds__(256, 2)
void gemm_out(const __half* __restrict__ A, const __half* __restrict__ W,
              float* __restrict__ C, const float* __restrict__ bias)
{
    extern __shared__ __align__(1024) char dsm[];
    const int bm0 = blockIdx.y * 128;
    const int bn0 = blockIdx.x * 128;

    float acc[2][8][4];
#pragma unroll
    for (int a = 0; a < 2; ++a)
#pragma unroll
        for (int b = 0; b < 8; ++b)
#pragma unroll
            for (int c = 0; c < 4; ++c) acc[a][b][c] = 0.0f;

    gemm_core(A, W, bm0, bn0, DMODEL, dsm, acc);

    const int wid = (int)threadIdx.x >> 5;
    const int lid = (int)threadIdx.x & 31;
    const int wr = wid >> 1, wc = wid & 1;

#pragma unroll
    for (int mt = 0; mt < 2; ++mt) {
        int row0 = bm0 + wr * 32 + mt * 16 + (lid >> 2);
#pragma unroll
        for (int nt = 0; nt < 8; ++nt) {
            int col = bn0 + wc * 64 + nt * 8 + (lid & 3) * 2;
            float bx = bias[col], by = bias[col + 1];
            float2 v0, v1;
            v0.x = acc[mt][nt][0] + bx; v0.y = acc[mt][nt][1] + by;
            v1.x = acc[mt][nt][2] + bx; v1.y = acc[mt][nt][3] + by;
            *(float2*)(C + (size_t)row0 * DMODEL + col)       = v0;
            *(float2*)(C + (size_t)(row0 + 8) * DMODEL + col) = v1;
        }
    }
}

// ====================== HMMA flash attention (fp16) ========================
// Q single fp16 (32KB), K/V double-buffered (2 x 32KB). P hi/lo in-register.
// R13-proven ordering: two syncs per KV tile, load issued before wait.
#define FA_SM_Q  0
#define FA_SM_ST 32768
#define FA_STAGE 32768            // K 16KB + V 16KB
#define FA_SMEM  98304

__global__ __launch_bounds__(256)
void flash_hmma(const __half* __restrict__ Qh, const __half* __restrict__ Kh,
                const __half* __restrict__ Vh, __half* __restrict__ Chi)
{
    extern __shared__ __align__(1024) char dsm[];
    const uint32_t smbase = smem_u32(dsm);

    const int tid = threadIdx.x;
    const int w   = tid >> 5;
    const int lid = tid & 31;

    const int qt = blockIdx.x;
    const int h  = blockIdx.y;
    const int bb = blockIdx.z;
    const int tQ = qt * 128;
    const int hc = h * HDIM;
    const int nkt = 2 * qt + 2;

    // ---- hoisted loader constants ----
    const int lrow  = tid >> 4;          // 0..15
    const int ls16  = tid & 15;
    const int lchnk = ls16 >> 3;
    const int lwi   = ls16 & 7;
    const uint32_t lsw =
        (uint32_t)((lrow * 128 + lwi * 16) ^ ((lrow << 4) & 0x70));
    const size_t lsrc0 =
        ((size_t)(bb * SEQ + lrow)) * DMODEL + hc + lchnk * 64 + lwi * 8;
    const size_t lstep = (size_t)16 * DMODEL;     // 16 rows per slot

    auto load_Q = [&]() {
        const __half* sQ = Qh + lsrc0 + (size_t)tQ * DMODEL;
        const uint32_t dq = smbase + FA_SM_Q + lchnk * 16384 + lsw;
#pragma unroll
        for (int it = 0; it < 8; ++it)
            cp_async16(dq + it * 2048, sQ + it * lstep);
    };
    auto load_KV = [&](int kt2, int st) {
        const size_t koff = lsrc0 + (size_t)(kt2 * 64) * DMODEL;
        const uint32_t dk = smbase + FA_SM_ST + st * FA_STAGE
                            + lchnk * 8192 + lsw;
        const uint32_t dv = dk + 16384;
        const __half* sK = Kh + koff;
        const __half* sV = Vh + koff;
#pragma unroll
        for (int it = 0; it < 4; ++it) {
            cp_async16(dk + it * 2048, sK + it * lstep);
            cp_async16(dv + it * 2048, sV + it * lstep);
        }
    };

    const uint32_t swXor = (uint32_t)((lid & 7) << 4);
    const uint32_t aRow  = (uint32_t)((w * 16 + (lid & 15)) * 128);
    const uint32_t aCol  = (lid & 16) ? 16u : 0u;
    uint32_t bRow[4];
#pragma unroll
    for (int g = 0; g < 4; ++g)
        bRow[g] = (uint32_t)((g * 16 + (lid & 7) + ((lid & 16) ? 8 : 0)) * 128);
    const uint32_t bCol  = (lid & 8) ? 16u : 0u;
    const uint32_t vRow  = (uint32_t)((lid & 15) * 128);
    const uint32_t vCol  = (lid & 16) ? 16u : 0u;

    float cacc[16][4];
#pragma unroll
    for (int i = 0; i < 16; ++i)
#pragma unroll
        for (int j = 0; j < 4; ++j) cacc[i][j] = 0.0f;
    float mrun[2] = {-1e30f, -1e30f};
    float lsum[2] = {0.0f, 0.0f};

    const int wrow = qt * 128 + w * 16;

    load_Q();
    load_KV(0, 0);
    cp_commit();

    for (int kt = 0; kt < nkt; ++kt) {
        const int s = kt & 1;
        __syncthreads();
        if (kt + 1 < nkt) { load_KV(kt + 1, s ^ 1); cp_commit(); cp_wait1(); }
        else              { cp_wait0(); }
        __syncthreads();

        const bool skip = (kt * 64 > wrow + 15);
        if (skip) continue;

        const uint32_t sK = smbase + FA_SM_ST + s * FA_STAGE;
        const uint32_t sV = sK + 16384;

        // ---- S = Q K^T (single pass) ----
        float sacc[8][4];
#pragma unroll
        for (int i = 0; i < 8; ++i)
#pragma unroll
            for (int j = 0; j < 4; ++j) sacc[i][j] = 0.0f;

#pragma unroll
        for (int t = 0; t < 8; ++t) {
            const uint32_t cb  = (uint32_t)((t & 3) * 32);
            const uint32_t qch = (uint32_t)((t >> 2) * 16384);
            const uint32_t kch = (uint32_t)((t >> 2) * 8192);
            uint32_t qf[4], kb[4][4];
            LDMX4(qf[0], qf[1], qf[2], qf[3],
                  smbase + FA_SM_Q + qch + aRow + ((cb + aCol) ^ swXor));
#pragma unroll
            for (int g = 0; g < 4; ++g)
                LDMX4(kb[g][0], kb[g][1], kb[g][2], kb[g][3],
                      sK + kch + bRow[g] + ((cb + bCol) ^ swXor));
#pragma unroll
            for (int g = 0; g < 4; ++g) {
                mma_f16(sacc[2 * g],     qf, kb[g][0], kb[g][1]);
                mma_f16(sacc[2 * g + 1], qf, kb[g][2], kb[g][3]);
            }
        }

        // ---- online softmax (exp2 domain) ----
        const bool need_mask = (kt * 64 + 63 > wrow);
#pragma unroll
        for (int i = 0; i < 2; ++i) {
            const int qr = wrow + (lid >> 2) + 8 * i;
            if (need_mask) {
#pragma unroll
                for (int nt = 0; nt < 8; ++nt) {
                    int c0 = kt * 64 + nt * 8 + (lid & 3) * 2;
                    if (c0     > qr) sacc[nt][2 * i]     = -1e30f;
                    if (c0 + 1 > qr) sacc[nt][2 * i + 1] = -1e30f;
                }
            }
            float mx = -1e30f;
#pragma unroll
            for (int nt = 0; nt < 8; ++nt)
                mx = fmaxf(mx, fmaxf(sacc[nt][2 * i], sacc[nt][2 * i + 1]));
            mx = fmaxf(mx, __shfl_xor_sync(0xffffffffu, mx, 1));
            mx = fmaxf(mx, __shfl_xor_sync(0xffffffffu, mx, 2));

            float mnew  = fmaxf(mrun[i], mx);
            float alpha = ex2(mrun[i] - mnew);
            float rs = 0.0f;
#pragma unroll
            for (int nt = 0; nt < 8; ++nt) {
                float p0 = ex2(sacc[nt][2 * i]     - mnew);
                float p1 = ex2(sacc[nt][2 * i + 1] - mnew);
                sacc[nt][2 * i] = p0; sacc[nt][2 * i + 1] = p1;
                rs += p0 + p1;
            }
            rs += __shfl_xor_sync(0xffffffffu, rs, 1);
            rs += __shfl_xor_sync(0xffffffffu, rs, 2);
            lsum[i] = lsum[i] * alpha + rs;
            mrun[i] = mnew;
#pragma unroll
            for (int nt = 0; nt < 16; ++nt) {
                cacc[nt][2 * i]     *= alpha;
                cacc[nt][2 * i + 1] *= alpha;
            }
        }

        // ---- O += P V (P hi/lo dual pass, in-register) ----
#pragma unroll
        for (int t = 0; t < 4; ++t) {
            uint32_t ph[4], pl[4];
#pragma unroll
            for (int u = 0; u < 4; ++u) {
                int tile = 2 * t + (u >> 1);
                int r0   = (u & 1) * 2;
                float x = sacc[tile][r0], y = sacc[tile][r0 + 1];
                __half hx = __float2half_rn(x), hy = __float2half_rn(y);
                __half lx = __float2half_rn(x - __half2float(hx));
                __half ly = __float2half_rn(y - __half2float(hy));
                ph[u] = pack_h2(hx, hy);
                pl[u] = pack_h2(lx, ly);
            }
            uint32_t pha[4] = {ph[0], ph[1], ph[2], ph[3]};
            uint32_t pla[4] = {pl[0], pl[1], pl[2], pl[3]};
            const uint32_t vt = (uint32_t)(t * 2048);
#pragma unroll
            for (int j = 0; j < 8; ++j) {
                const uint32_t cb = (uint32_t)((j & 3) * 32) + vCol;
                uint32_t b0, b1, b2, b3;
                LDMX4T(b0, b1, b2, b3,
                       sV + (uint32_t)((j >> 2) * 8192) + vRow + vt + (cb ^ swXor));
                mma_f16(cacc[2 * j],     pha, b0, b1);
                mma_f16(cacc[2 * j + 1], pha, b2, b3);
                mma_f16(cacc[2 * j],     pla, b0, b1);
                mma_f16(cacc[2 * j + 1], pla, b2, b3);
            }
        }
    }

    // epilogue: normalize + fp16 ctx store
#pragma unroll
    for (int i = 0; i < 2; ++i) {
        float inv = 1.0f / lsum[i];
        int row = tQ + w * 16 + (lid >> 2) + 8 * i;
        size_t gbase = ((size_t)(bb * SEQ + row)) * DMODEL + hc;
#pragma unroll
        for (int nt = 0; nt < 16; ++nt) {
            int col = nt * 8 + (lid & 3) * 2;
            float v0 = cacc[nt][2 * i]     * inv;
            float v1 = cacc[nt][2 * i + 1] * inv;
            *(uint32_t*)(Chi + gbase + col) =
                pack_h2(__float2half_rn(v0), __float2half_rn(v1));
        }
    }
}

// ---------------------------------------------------------------------------
extern "C" void kernel_launch(void* const* d_in, const int* in_sizes, int n_in,
                              void* d_out, int out_size)
{
    (void)in_sizes; (void)n_in; (void)out_size;
    const float* x  = (const float*)d_in[0];
    const float* Wq = (const float*)d_in[1];
    const float* Wk = (const float*)d_in[2];
    const float* Wv = (const float*)d_in[3];
    const float* Wo = (const float*)d_in[4];
    const float* bo = (const float*)d_in[5];
    float* out = (float*)d_out;

    __half *qh, *kh, *vh, *xh, *chi, *wh;
    cudaGetSymbolAddress((void**)&qh, g_qh);
    cudaGetSymbolAddress((void**)&kh, g_kh);
    cudaGetSymbolAddress((void**)&vh, g_vh);
    cudaGetSymbolAddress((void**)&xh, g_xh);
    cudaGetSymbolAddress((void**)&chi, g_chi);
    cudaGetSymbolAddress((void**)&wh, g_wh);

    const size_t WN = (size_t)DMODEL * DMODEL;
    const float qscale = 0.08838834764831845f * 1.4426950408889634f;

    cudaFuncSetAttribute(gemm_qkv,
                         cudaFuncAttributeMaxDynamicSharedMemorySize, GEMM_SMEM);
    cudaFuncSetAttribute(gemm_out,
                         cudaFuncAttributeMaxDynamicSharedMemorySize, GEMM_SMEM);
    cudaFuncSetAttribute(flash_hmma,
                         cudaFuncAttributeMaxDynamicSharedMemorySize, FA_SMEM);

    // 1) fused convert: x and weights -> fp16 (4 float4 per thread)
    int ntot = NX4 + 4 * NW4;                       // 2^23
    split_all<<<ntot / 1024, 256>>>((const float4*)x,
        (const float4*)Wq, (const float4*)Wk, (const float4*)Wv, (const float4*)Wo,
        (__half2*)xh, (__half2*)wh);

    // 2) fused QKV projection (single pass)
    dim3 qkvgrid(3 * DMODEL / 128, M_TOK / 128);    // (48, 64)
    gemm_qkv<<<qkvgrid, 256, GEMM_SMEM>>>(xh, wh, qh, kh, vh, qscale);

    // 3) flash attention (HMMA fp16, Q single / P dual) -> fp16 ctx
    dim3 fgrid(SEQ / 128, NHEADS, BATCH);
    flash_hmma<<<fgrid, 256, FA_SMEM>>>(qh, kh, vh, chi);

    // 4) output projection + bias (single pass, fp32 out)
    dim3 ogrid(DMODEL / 128, M_TOK / 128);          // (16, 64)
    gemm_out<<<ogrid, 256, GEMM_SMEM>>>(chi, wh + 3 * WN, out, bo);
}

// round 16
// speedup vs baseline: 1.0385x; 1.0385x over previous
#include <cuda_runtime.h>
#include <cuda_bf16.h>
#include <cuda_fp16.h>
#include <cstdint>
#include <math.h>

#define M_TOK   8192      // 4 * 2048 tokens
#define DMODEL  2048
#define NHEADS  16
#define HDIM    128
#define SEQ     2048
#define BATCH   4

// ---------------- scratch (static device allocations; no cudaMalloc) -------
__device__ __half g_qh[(size_t)M_TOK * DMODEL];
__device__ __half g_kh[(size_t)M_TOK * DMODEL];
__device__ __half g_vh[(size_t)M_TOK * DMODEL];

__device__ __half g_xh[(size_t)M_TOK * DMODEL];
__device__ __half g_chi[(size_t)M_TOK * DMODEL];
__device__ __half g_wh[(size_t)4 * DMODEL * DMODEL];

// ============================ helpers ======================================
__device__ __forceinline__ uint32_t smem_u32(const void* p) {
    uint32_t a;
    asm("{ .reg .u64 t; cvta.to.shared.u64 t, %1; cvt.u32.u64 %0, t; }"
        : "=r"(a) : "l"(p));
    return a;
}
__device__ __forceinline__ void cp_async16(uint32_t dst, const void* src) {
    asm volatile("cp.async.cg.shared.global [%0], [%1], 16;"
                 :: "r"(dst), "l"(src) : "memory");
}
__device__ __forceinline__ void cp_commit() {
    asm volatile("cp.async.commit_group;" ::: "memory");
}
__device__ __forceinline__ void cp_wait0() {
    asm volatile("cp.async.wait_group 0;" ::: "memory");
}
__device__ __forceinline__ void cp_wait1() {
    asm volatile("cp.async.wait_group 1;" ::: "memory");
}
__device__ __forceinline__ void cp_wait2() {
    asm volatile("cp.async.wait_group 2;" ::: "memory");
}
__device__ __forceinline__ float ex2(float x) {
    float y; asm("ex2.approx.f32 %0, %1;" : "=f"(y) : "f"(x)); return y;
}
__device__ __forceinline__ void mma_f16(float* d,
                                        const uint32_t* a, uint32_t b0, uint32_t b1) {
    asm volatile("mma.sync.aligned.m16n8k16.row.col.f32.f16.f16.f32 "
                 "{%0,%1,%2,%3}, {%4,%5,%6,%7}, {%8,%9}, {%0,%1,%2,%3};"
                 : "+f"(d[0]), "+f"(d[1]), "+f"(d[2]), "+f"(d[3])
                 : "r"(a[0]), "r"(a[1]), "r"(a[2]), "r"(a[3]), "r"(b0), "r"(b1));
}
#define LDMX4(r0, r1, r2, r3, addr)                                          \
    asm volatile("ldmatrix.sync.aligned.m8n8.x4.shared.b16 {%0,%1,%2,%3}, [%4];" \
                 : "=r"(r0), "=r"(r1), "=r"(r2), "=r"(r3) : "r"(addr))
#define LDMX4T(r0, r1, r2, r3, addr)                                         \
    asm volatile("ldmatrix.sync.aligned.m8n8.x4.trans.shared.b16 {%0,%1,%2,%3}, [%4];" \
                 : "=r"(r0), "=r"(r1), "=r"(r2), "=r"(r3) : "r"(addr))

__device__ __forceinline__ uint32_t pack_h2(__half a, __half b) {
    __half2 h = __halves2half2(a, b);
    return *(uint32_t*)&h;
}

// ================= fused fp32 -> fp16 convert (x and weights) ==============
// 4 float4 per thread, block-tiled: off = blk*1024 + u*256 + tid.
// Per instruction, consecutive threads hit consecutive float4 (coalesced).
// Region boundaries (NX4 = 2^22, NW4 = 2^20) are multiples of 1024, so no
// block straddles tensors.
#define NX4 ((int)((size_t)M_TOK * DMODEL / 4))        // 4,194,304 = 2^22
#define NW4 ((int)((size_t)DMODEL * DMODEL / 4))       // 1,048,576 = 2^20

__global__ __launch_bounds__(256)
void split_all(const float4* __restrict__ x,
               const float4* __restrict__ Wq, const float4* __restrict__ Wk,
               const float4* __restrict__ Wv, const float4* __restrict__ Wo,
               __half2* __restrict__ xh, __half2* __restrict__ wh)
{
    int base = blockIdx.x * 1024;
    const float4* src;
    __half2* dst;
    int rbase;
    if (base < NX4) {
        src = x; rbase = base; dst = xh;
    } else {
        int r = base - NX4;
        int j = r >> 20;
        rbase = r & (NW4 - 1);
        src = (j == 0) ? Wq : (j == 1) ? Wk : (j == 2) ? Wv : Wo;
        dst = wh + (size_t)j * NW4 * 2;
    }
    int off0 = rbase + threadIdx.x;
    float4 v[4];
#pragma unroll
    for (int u = 0; u < 4; ++u) v[u] = src[off0 + u * 256];
#pragma unroll
    for (int u = 0; u < 4; ++u) {
        int o = off0 + u * 256;
        dst[2 * o]     = __halves2half2(__float2half_rn(v[u].x),
                                        __float2half_rn(v[u].y));
        dst[2 * o + 1] = __halves2half2(__float2half_rn(v[u].z),
                                        __float2half_rn(v[u].w));
    }
}

// === HMMA GEMM core: CTA 128x128, GBK=64, single-pass, 3-stage, 2 CTA/SM ===
// R13-proven ordering: issue load(i+2) FIRST, then wait for chunk i, sync,
// compute, sync. (Two barriers/chunk; load issue overlaps the wait.)
#define GBK 64
#define B_OFF   16384
#define STAGE   32768
#define GEMM_SMEM (3 * STAGE)        // 98304 -> 2 CTAs/SM

__device__ __forceinline__ void gemm_core(
    const __half* __restrict__ A, const __half* __restrict__ B,
    int bm0, int bn0, int K, char* dsm, float acc[2][8][4])
{
    const int tid = threadIdx.x;
    const int wid = tid >> 5;
    const int lid = tid & 31;
    const int wr = wid >> 1;             // 0..3, m-offset wr*32
    const int wc = wid & 1;              // 0..1, n-offset wc*64
    const uint32_t smbase = smem_u32(dsm);

    uint32_t aRaw[2], aXor[2], bRaw[4], bXor[4];
#pragma unroll
    for (int mt = 0; mt < 2; ++mt) {
        int row = wr * 32 + mt * 16 + (lid & 15);
        aRaw[mt] = (uint32_t)(row * 128 + ((lid & 16) ? 16 : 0));
        aXor[mt] = (uint32_t)((row << 4) & 0x70);
    }
#pragma unroll
    for (int g = 0; g < 4; ++g) {
        int nrow = wc * 64 + g * 16 + (lid & 7) + ((lid & 16) ? 8 : 0);
        bRaw[g] = (uint32_t)(nrow * 128 + ((lid & 8) ? 16 : 0));
        bXor[g] = (uint32_t)((nrow << 4) & 0x70);
    }

    // ---- hoisted loader constants (A 1024 + B 1024 16B units, 8/thread) ----
    const int rbase = tid >> 3;          // 0..31
    const int s16   = tid & 7;
    const uint32_t dstc =
        (uint32_t)((rbase * 128 + s16 * 16) ^ ((rbase << 4) & 0x70));
    const __half* sA = A + (size_t)(bm0 + rbase) * K + s16 * 8;
    const __half* sB = B + (size_t)(bn0 + rbase) * K + s16 * 8;
    const size_t rstep = (size_t)32 * K;     // 32 rows per slot

    auto load_chunk = [&](int chunk, int stage) {
        const int k0 = chunk * GBK;
        const uint32_t db = smbase + stage * STAGE + dstc;
#pragma unroll
        for (int it = 0; it < 4; ++it) {
            cp_async16(db + it * 4096,         sA + it * rstep + k0);
            cp_async16(db + B_OFF + it * 4096, sB + it * rstep + k0);
        }
        cp_commit();
    };

    const int nchunk = K / GBK;          // 32
    load_chunk(0, 0);
    load_chunk(1, 1);

    for (int i = 0; i < nchunk; ++i) {
        const int st = i % 3;
        if (i + 2 < nchunk) {
            load_chunk(i + 2, (i + 2) % 3);
            cp_wait2();                  // chunk i arrived (i+1, i+2 in flight)
        } else if (i + 1 < nchunk) {
            cp_wait1();
        } else {
            cp_wait0();
        }
        __syncthreads();

        const uint32_t sb = smbase + st * STAGE;

#pragma unroll
        for (int ks = 0; ks < 4; ++ks) {
            const uint32_t kd = ks * 32;
            uint32_t ah[2][4], bfr[8][2];
#pragma unroll
            for (int mt = 0; mt < 2; ++mt)
                LDMX4(ah[mt][0], ah[mt][1], ah[mt][2], ah[mt][3],
                      sb + ((aRaw[mt] + kd) ^ aXor[mt]));
#pragma unroll
            for (int g = 0; g < 4; ++g)
                LDMX4(bfr[2 * g][0], bfr[2 * g][1], bfr[2 * g + 1][0], bfr[2 * g + 1][1],
                      sb + B_OFF + ((bRaw[g] + kd) ^ bXor[g]));
#pragma unroll
            for (int mt = 0; mt < 2; ++mt)
#pragma unroll
                for (int nt = 0; nt < 8; ++nt)
                    mma_f16(acc[mt][nt], ah[mt], bfr[nt][0], bfr[nt][1]);
        }
        __syncthreads();   // stage st must be drained before iter i+1 reloads it
    }
}

// ---- fused QKV projection: B rows = stacked [Wq; Wk; Wv], single pass ----
__global__ __launch_bounds__(256, 2)
void gemm_qkv(const __half* __restrict__ Xh, const __half* __restrict__ W,
              __half* __restrict__ Qh, __half* __restrict__ Kh,
              __half* __restrict__ Vh, float qscale)
{
    extern __shared__ __align__(1024) char dsm[];
    const int bm0 = blockIdx.y * 128;
    const int bn0 = blockIdx.x * 128;    // 0..6016
    const int j = bn0 >> 11;             // 0=Q 1=K 2=V

    float acc[2][8][4];
#pragma unroll
    for (int a = 0; a < 2; ++a)
#pragma unroll
        for (int b = 0; b < 8; ++b)
#pragma unroll
            for (int c = 0; c < 4; ++c) acc[a][b][c] = 0.0f;

    gemm_core(Xh, W, bm0, bn0, DMODEL, dsm, acc);

    const int ncol0 = bn0 & 2047;
    __half* dst = (j == 0) ? Qh : (j == 1) ? Kh : Vh;
    const float sc = (j == 0) ? qscale : 1.0f;
    const int wid = (int)threadIdx.x >> 5;
    const int lid = (int)threadIdx.x & 31;
    const int wr = wid >> 1, wc = wid & 1;

#pragma unroll
    for (int mt = 0; mt < 2; ++mt) {
        int row0 = bm0 + wr * 32 + mt * 16 + (lid >> 2);
#pragma unroll
        for (int nt = 0; nt < 8; ++nt) {
            int col = ncol0 + wc * 64 + nt * 8 + (lid & 3) * 2;
            __half h0 = __float2half_rn(acc[mt][nt][0] * sc);
            __half h1 = __float2half_rn(acc[mt][nt][1] * sc);
            __half h2 = __float2half_rn(acc[mt][nt][2] * sc);
            __half h3 = __float2half_rn(acc[mt][nt][3] * sc);
            *(uint32_t*)(dst + (size_t)row0 * DMODEL + col)       = pack_h2(h0, h1);
            *(uint32_t*)(dst + (size_t)(row0 + 8) * DMODEL + col) = pack_h2(h2, h3);
        }
    }
}

// ---- output projection: single-pass fp16 ctx, fp32 out + bias ----
__global__ __launch_bounds__(256, 2)
void gemm_out(const __half* __restrict__ A, const __half* __restrict__ W,
              float* __restrict__ C, const float* __restrict__ bias)
{
    extern __shared__ __align__(1024) char dsm[];
    const int bm0 = blockIdx.y * 128;
    const int bn0 = blockIdx.x * 128;

    float acc[2][8][4];
#pragma unroll
    for (int a = 0; a < 2; ++a)
#pragma unroll
        for (int b = 0; b < 8; ++b)
#pragma unroll
            for (int c = 0; c < 4; ++c) acc[a][b][c] = 0.0f;

    gemm_core(A, W, bm0, bn0, DMODEL, dsm, acc);

    const int wid = (int)threadIdx.x >> 5;
    const int lid = (int)threadIdx.x & 31;
    const int wr = wid >> 1, wc = wid & 1;

#pragma unroll
    for (int mt = 0; mt < 2; ++mt) {
        int row0 = bm0 + wr * 32 + mt * 16 + (lid >> 2);
#pragma unroll
        for (int nt = 0; nt < 8; ++nt) {
            int col = bn0 + wc * 64 + nt * 8 + (lid & 3) * 2;
            float bx = bias[col], by = bias[col + 1];
            float2 v0, v1;
            v0.x = acc[mt][nt][0] + bx; v0.y = acc[mt][nt][1] + by;
            v1.x = acc[mt][nt][2] + bx; v1.y = acc[mt][nt][3] + by;
            *(float2*)(C + (size_t)row0 * DMODEL + col)       = v0;
            *(float2*)(C + (size_t)(row0 + 8) * DMODEL + col) = v1;
        }
    }
}

// ====================== HMMA flash attention (fp16) ========================
// Q single fp16 (32KB), K/V double-buffered (2 x 32KB). P hi/lo in-register.
// R13-proven ordering: two syncs per KV tile, load issued before wait.
#define FA_SM_Q  0
#define FA_SM_ST 32768
#define FA_STAGE 32768            // K 16KB + V 16KB
#define FA_SMEM  98304

__global__ __launch_bounds__(256)
void flash_hmma(const __half* __restrict__ Qh, const __half* __restrict__ Kh,
                const __half* __restrict__ Vh, __half* __restrict__ Chi)
{
    extern __shared__ __align__(1024) char dsm[];
    const uint32_t smbase = smem_u32(dsm);

    const int tid = threadIdx.x;
    const int w   = tid >> 5;
    const int lid = tid & 31;

    const int qt = blockIdx.x;
    const int h  = blockIdx.y;
    const int bb = blockIdx.z;
    const int tQ = qt * 128;
    const int hc = h * HDIM;
    const int nkt = 2 * qt + 2;

    // ---- hoisted loader constants ----
    const int lrow  = tid >> 4;          // 0..15
    const int ls16  = tid & 15;
    const int lchnk = ls16 >> 3;
    const int lwi   = ls16 & 7;
    const uint32_t lsw =
        (uint32_t)((lrow * 128 + lwi * 16) ^ ((lrow << 4) & 0x70));
    const size_t lsrc0 =
        ((size_t)(bb * SEQ + lrow)) * DMODEL + hc + lchnk * 64 + lwi * 8;
    const size_t lstep = (size_t)16 * DMODEL;     // 16 rows per slot

    auto load_Q = [&]() {
        const __half* sQ = Qh + lsrc0 + (size_t)tQ * DMODEL;
        const uint32_t dq = smbase + FA_SM_Q + lchnk * 16384 + lsw;
#pragma unroll
        for (int it = 0; it < 8; ++it)
            cp_async16(dq + it * 2048, sQ + it * lstep);
    };
    auto load_KV = [&](int kt2, int st) {
        const size_t koff = lsrc0 + (size_t)(kt2 * 64) * DMODEL;
        const uint32_t dk = smbase + FA_SM_ST + st * FA_STAGE
                            + lchnk * 8192 + lsw;
        const uint32_t dv = dk + 16384;
        const __half* sK = Kh + koff;
        const __half* sV = Vh + koff;
#pragma unroll
        for (int it = 0; it < 4; ++it) {
            cp_async16(dk + it * 2048, sK + it * lstep);
            cp_async16(dv + it * 2048, sV + it * lstep);
        }
    };

    const uint32_t swXor = (uint32_t)((lid & 7) << 4);
    const uint32_t aRow  = (uint32_t)((w * 16 + (lid & 15)) * 128);
    const uint32_t aCol  = (lid & 16) ? 16u : 0u;
    uint32_t bRow[4];
#pragma unroll
    for (int g = 0; g < 4; ++g)
        bRow[g] = (uint32_t)((g * 16 + (lid & 7) + ((lid & 16) ? 8 : 0)) * 128);
    const uint32_t bCol  = (lid & 8) ? 16u : 0u;
    const uint32_t vRow  = (uint32_t)((lid & 15) * 128);
    const uint32_t vCol  = (lid & 16) ? 16u : 0u;

    float cacc[16][4];
#pragma unroll
    for (int i = 0; i < 16; ++i)
#pragma unroll
        for (int j = 0; j < 4; ++j) cacc[i][j] = 0.0f;
    float mrun[2] = {-1e30f, -1e30f};
    float lsum[2] = {0.0f, 0.0f};

    const int wrow = qt * 128 + w * 16;

    load_Q();
    load_KV(0, 0);
    cp_commit();

    for (int kt = 0; kt < nkt; ++kt) {
        const int s = kt & 1;
        __syncthreads();
        if (kt + 1 < nkt) { load_KV(kt + 1, s ^ 1); cp_commit(); cp_wait1(); }
        else              { cp_wait0(); }
        __syncthreads();

        const bool skip = (kt * 64 > wrow + 15);
        if (skip) continue;

        const uint32_t sK = smbase + FA_SM_ST + s * FA_STAGE;
        const uint32_t sV = sK + 16384;

        // ---- S = Q K^T (single pass) ----
        float sacc[8][4];
#pragma unroll
        for (int i = 0; i < 8; ++i)
#pragma unroll
            for (int j = 0; j < 4; ++j) sacc[i][j] = 0.0f;

#pragma unroll
        for (int t = 0; t < 8; ++t) {
            const uint32_t cb  = (uint32_t)((t & 3) * 32);
            const uint32_t qch = (uint32_t)((t >> 2) * 16384);
            const uint32_t kch = (uint32_t)((t >> 2) * 8192);
            uint32_t qf[4], kb[4][4];
            LDMX4(qf[0], qf[1], qf[2], qf[3],
                  smbase + FA_SM_Q + qch + aRow + ((cb + aCol) ^ swXor));
#pragma unroll
            for (int g = 0; g < 4; ++g)
                LDMX4(kb[g][0], kb[g][1], kb[g][2], kb[g][3],
                      sK + kch + bRow[g] + ((cb + bCol) ^ swXor));
#pragma unroll
            for (int g = 0; g < 4; ++g) {
                mma_f16(sacc[2 * g],     qf, kb[g][0], kb[g][1]);
                mma_f16(sacc[2 * g + 1], qf, kb[g][2], kb[g][3]);
            }
        }

        // ---- online softmax (exp2 domain) ----
        const bool need_mask = (kt * 64 + 63 > wrow);
#pragma unroll
        for (int i = 0; i < 2; ++i) {
            const int qr = wrow + (lid >> 2) + 8 * i;
            if (need_mask) {
#pragma unroll
                for (int nt = 0; nt < 8; ++nt) {
                    int c0 = kt * 64 + nt * 8 + (lid & 3) * 2;
                    if (c0     > qr) sacc[nt][2 * i]     = -1e30f;
                    if (c0 + 1 > qr) sacc[nt][2 * i + 1] = -1e30f;
                }
            }
            float mx = -1e30f;
#pragma unroll
            for (int nt = 0; nt < 8; ++nt)
                mx = fmaxf(mx, fmaxf(sacc[nt][2 * i], sacc[nt][2 * i + 1]));
            mx = fmaxf(mx, __shfl_xor_sync(0xffffffffu, mx, 1));
            mx = fmaxf(mx, __shfl_xor_sync(0xffffffffu, mx, 2));

            float mnew  = fmaxf(mrun[i], mx);
            float alpha = ex2(mrun[i] - mnew);
            float rs = 0.0f;
#pragma unroll
            for (int nt = 0; nt < 8; ++nt) {
                float p0 = ex2(sacc[nt][2 * i]     - mnew);
                float p1 = ex2(sacc[nt][2 * i + 1] - mnew);
                sacc[nt][2 * i] = p0; sacc[nt][2 * i + 1] = p1;
                rs += p0 + p1;
            }
            rs += __shfl_xor_sync(0xffffffffu, rs, 1);
            rs += __shfl_xor_sync(0xffffffffu, rs, 2);
            lsum[i] = lsum[i] * alpha + rs;
            mrun[i] = mnew;
#pragma unroll
            for (int nt = 0; nt < 16; ++nt) {
                cacc[nt][2 * i]     *= alpha;
                cacc[nt][2 * i + 1] *= alpha;
            }
        }

        // ---- O += P V (P hi/lo dual pass, in-register) ----
#pragma unroll
        for (int t = 0; t < 4; ++t) {
            uint32_t ph[4], pl[4];
#pragma unroll
            for (int u = 0; u < 4; ++u) {
                int tile = 2 * t + (u >> 1);
                int r0   = (u & 1) * 2;
                float x = sacc[tile][r0], y = sacc[tile][r0 + 1];
                __half hx = __float2half_rn(x), hy = __float2half_rn(y);
                __half lx = __float2half_rn(x - __half2float(hx));
                __half ly = __float2half_rn(y - __half2float(hy));
                ph[u] = pack_h2(hx, hy);
                pl[u] = pack_h2(lx, ly);
            }
            uint32_t pha[4] = {ph[0], ph[1], ph[2], ph[3]};
            uint32_t pla[4] = {pl[0], pl[1], pl[2], pl[3]};
            const uint32_t vt = (uint32_t)(t * 2048);
#pragma unroll
            for (int j = 0; j < 8; ++j) {
                const uint32_t cb = (uint32_t)((j & 3) * 32) + vCol;
                uint32_t b0, b1, b2, b3;
                LDMX4T(b0, b1, b2, b3,
                       sV + (uint32_t)((j >> 2) * 8192) + vRow + vt + (cb ^ swXor));
                mma_f16(cacc[2 * j],     pha, b0, b1);
                mma_f16(cacc[2 * j + 1], pha, b2, b3);
                mma_f16(cacc[2 * j],     pla, b0, b1);
                mma_f16(cacc[2 * j + 1], pla, b2, b3);
            }
        }
    }

    // epilogue: normalize + fp16 ctx store
#pragma unroll
    for (int i = 0; i < 2; ++i) {
        float inv = 1.0f / lsum[i];
        int row = tQ + w * 16 + (lid >> 2) + 8 * i;
        size_t gbase = ((size_t)(bb * SEQ + row)) * DMODEL + hc;
#pragma unroll
        for (int nt = 0; nt < 16; ++nt) {
            int col = nt * 8 + (lid & 3) * 2;
            float v0 = cacc[nt][2 * i]     * inv;
            float v1 = cacc[nt][2 * i + 1] * inv;
            *(uint32_t*)(Chi + gbase + col) =
                pack_h2(__float2half_rn(v0), __float2half_rn(v1));
        }
    }
}

// ---------------------------------------------------------------------------
extern "C" void kernel_launch(void* const* d_in, const int* in_sizes, int n_in,
                              void* d_out, int out_size)
{
    (void)in_sizes; (void)n_in; (void)out_size;
    const float* x  = (const float*)d_in[0];
    const float* Wq = (const float*)d_in[1];
    const float* Wk = (const float*)d_in[2];
    const float* Wv = (const float*)d_in[3];
    const float* Wo = (const float*)d_in[4];
    const float* bo = (const float*)d_in[5];
    float* out = (float*)d_out;

    __half *qh, *kh, *vh, *xh, *chi, *wh;
    cudaGetSymbolAddress((void**)&qh, g_qh);
    cudaGetSymbolAddress((void**)&kh, g_kh);
    cudaGetSymbolAddress((void**)&vh, g_vh);
    cudaGetSymbolAddress((void**)&xh, g_xh);
    cudaGetSymbolAddress((void**)&chi, g_chi);
    cudaGetSymbolAddress((void**)&wh, g_wh);

    const size_t WN = (size_t)DMODEL * DMODEL;
    const float qscale = 0.08838834764831845f * 1.4426950408889634f;

    cudaFuncSetAttribute(gemm_qkv,
                         cudaFuncAttributeMaxDynamicSharedMemorySize, GEMM_SMEM);
    cudaFuncSetAttribute(gemm_out,
                         cudaFuncAttributeMaxDynamicSharedMemorySize, GEMM_SMEM);
    cudaFuncSetAttribute(flash_hmma,
                         cudaFuncAttributeMaxDynamicSharedMemorySize, FA_SMEM);

    // 1) fused convert: x and weights -> fp16 (coalesced, 4 float4/thread)
    int ntot = NX4 + 4 * NW4;                       // 2^23
    split_all<<<ntot / 1024, 256>>>((const float4*)x,
        (const float4*)Wq, (const float4*)Wk, (const float4*)Wv, (const float4*)Wo,
        (__half2*)xh, (__half2*)wh);

    // 2) fused QKV projection (single pass)
    dim3 qkvgrid(3 * DMODEL / 128, M_TOK / 128);    // (48, 64)
    gemm_qkv<<<qkvgrid, 256, GEMM_SMEM>>>(xh, wh, qh, kh, vh, qscale);

    // 3) flash attention (HMMA fp16, Q single / P dual) -> fp16 ctx
    dim3 fgrid(SEQ / 128, NHEADS, BATCH);
    flash_hmma<<<fgrid, 256, FA_SMEM>>>(qh, kh, vh, chi);

    // 4) output projection + bias (single pass, fp32 out)
    dim3 ogrid(DMODEL / 128, M_TOK / 128);          // (16, 64)
    gemm_out<<<ogrid, 256, GEMM_SMEM>>>(chi, wh + 3 * WN, out, bo);
}

// round 17
// speedup vs baseline: 1.1319x; 1.0899x over previous
#include <cuda_runtime.h>
#include <cuda_bf16.h>
#include <cuda_fp16.h>
#include <cstdint>
#include <math.h>

#define M_TOK   8192      // 4 * 2048 tokens
#define DMODEL  2048
#define NHEADS  16
#define HDIM    128
#define SEQ     2048
#define BATCH   4

// ---------------- scratch (static device allocations; no cudaMalloc) -------
__device__ __half g_qh[(size_t)M_TOK * DMODEL];
__device__ __half g_kh[(size_t)M_TOK * DMODEL];
__device__ __half g_vh[(size_t)M_TOK * DMODEL];

__device__ __half g_xh[(size_t)M_TOK * DMODEL];
__device__ __half g_chi[(size_t)M_TOK * DMODEL];
__device__ __half g_wh[(size_t)4 * DMODEL * DMODEL];

// ============================ helpers ======================================
__device__ __forceinline__ uint32_t smem_u32(const void* p) {
    uint32_t a;
    asm("{ .reg .u64 t; cvta.to.shared.u64 t, %1; cvt.u32.u64 %0, t; }"
        : "=r"(a) : "l"(p));
    return a;
}
__device__ __forceinline__ void cp_async16(uint32_t dst, const void* src) {
    asm volatile("cp.async.cg.shared.global [%0], [%1], 16;"
                 :: "r"(dst), "l"(src) : "memory");
}
__device__ __forceinline__ void cp_commit() {
    asm volatile("cp.async.commit_group;" ::: "memory");
}
__device__ __forceinline__ void cp_wait0() {
    asm volatile("cp.async.wait_group 0;" ::: "memory");
}
__device__ __forceinline__ void cp_wait1() {
    asm volatile("cp.async.wait_group 1;" ::: "memory");
}
__device__ __forceinline__ void cp_wait2() {
    asm volatile("cp.async.wait_group 2;" ::: "memory");
}
__device__ __forceinline__ float ex2(float x) {
    float y; asm("ex2.approx.f32 %0, %1;" : "=f"(y) : "f"(x)); return y;
}
__device__ __forceinline__ void mma_f16(float* d,
                                        const uint32_t* a, uint32_t b0, uint32_t b1) {
    asm volatile("mma.sync.aligned.m16n8k16.row.col.f32.f16.f16.f32 "
                 "{%0,%1,%2,%3}, {%4,%5,%6,%7}, {%8,%9}, {%0,%1,%2,%3};"
                 : "+f"(d[0]), "+f"(d[1]), "+f"(d[2]), "+f"(d[3])
                 : "r"(a[0]), "r"(a[1]), "r"(a[2]), "r"(a[3]), "r"(b0), "r"(b1));
}
#define LDMX4(r0, r1, r2, r3, addr)                                          \
    asm volatile("ldmatrix.sync.aligned.m8n8.x4.shared.b16 {%0,%1,%2,%3}, [%4];" \
                 : "=r"(r0), "=r"(r1), "=r"(r2), "=r"(r3) : "r"(addr))
#define LDMX4T(r0, r1, r2, r3, addr)                                         \
    asm volatile("ldmatrix.sync.aligned.m8n8.x4.trans.shared.b16 {%0,%1,%2,%3}, [%4];" \
                 : "=r"(r0), "=r"(r1), "=r"(r2), "=r"(r3) : "r"(addr))

__device__ __forceinline__ uint32_t pack_h2(__half a, __half b) {
    __half2 h = __halves2half2(a, b);
    return *(uint32_t*)&h;
}

// ================= fused fp32 -> fp16 convert (x and weights) ==============
// Block-tiled, coalesced, 4 float4/thread (R16-proven).
#define NX4 ((int)((size_t)M_TOK * DMODEL / 4))        // 4,194,304 = 2^22
#define NW4 ((int)((size_t)DMODEL * DMODEL / 4))       // 1,048,576 = 2^20

__global__ __launch_bounds__(256)
void split_all(const float4* __restrict__ x,
               const float4* __restrict__ Wq, const float4* __restrict__ Wk,
               const float4* __restrict__ Wv, const float4* __restrict__ Wo,
               __half2* __restrict__ xh, __half2* __restrict__ wh)
{
    int base = blockIdx.x * 1024;
    const float4* src;
    __half2* dst;
    int rbase;
    if (base < NX4) {
        src = x; rbase = base; dst = xh;
    } else {
        int r = base - NX4;
        int j = r >> 20;
        rbase = r & (NW4 - 1);
        src = (j == 0) ? Wq : (j == 1) ? Wk : (j == 2) ? Wv : Wo;
        dst = wh + (size_t)j * NW4 * 2;
    }
    int off0 = rbase + threadIdx.x;
    float4 v[4];
#pragma unroll
    for (int u = 0; u < 4; ++u) v[u] = src[off0 + u * 256];
#pragma unroll
    for (int u = 0; u < 4; ++u) {
        int o = off0 + u * 256;
        dst[2 * o]     = __halves2half2(__float2half_rn(v[u].x),
                                        __float2half_rn(v[u].y));
        dst[2 * o + 1] = __halves2half2(__float2half_rn(v[u].z),
                                        __float2half_rn(v[u].w));
    }
}

// === HMMA GEMM core: CTA 128x128, GBK=64, single-pass, 3-stage, 2 CTA/SM ===
// R13-proven ordering (unchanged).
#define GBK 64
#define B_OFF   16384
#define STAGE   32768
#define GEMM_SMEM (3 * STAGE)        // 98304 -> 2 CTAs/SM

__device__ __forceinline__ void gemm_core(
    const __half* __restrict__ A, const __half* __restrict__ B,
    int bm0, int bn0, int K, char* dsm, float acc[2][8][4])
{
    const int tid = threadIdx.x;
    const int wid = tid >> 5;
    const int lid = tid & 31;
    const int wr = wid >> 1;             // 0..3, m-offset wr*32
    const int wc = wid & 1;              // 0..1, n-offset wc*64
    const uint32_t smbase = smem_u32(dsm);

    uint32_t aRaw[2], aXor[2], bRaw[4], bXor[4];
#pragma unroll
    for (int mt = 0; mt < 2; ++mt) {
        int row = wr * 32 + mt * 16 + (lid & 15);
        aRaw[mt] = (uint32_t)(row * 128 + ((lid & 16) ? 16 : 0));
        aXor[mt] = (uint32_t)((row << 4) & 0x70);
    }
#pragma unroll
    for (int g = 0; g < 4; ++g) {
        int nrow = wc * 64 + g * 16 + (lid & 7) + ((lid & 16) ? 8 : 0);
        bRaw[g] = (uint32_t)(nrow * 128 + ((lid & 8) ? 16 : 0));
        bXor[g] = (uint32_t)((nrow << 4) & 0x70);
    }

    const int rbase = tid >> 3;
    const int s16   = tid & 7;
    const uint32_t dstc =
        (uint32_t)((rbase * 128 + s16 * 16) ^ ((rbase << 4) & 0x70));
    const __half* sA = A + (size_t)(bm0 + rbase) * K + s16 * 8;
    const __half* sB = B + (size_t)(bn0 + rbase) * K + s16 * 8;
    const size_t rstep = (size_t)32 * K;

    auto load_chunk = [&](int chunk, int stage) {
        const int k0 = chunk * GBK;
        const uint32_t db = smbase + stage * STAGE + dstc;
#pragma unroll
        for (int it = 0; it < 4; ++it) {
            cp_async16(db + it * 4096,         sA + it * rstep + k0);
            cp_async16(db + B_OFF + it * 4096, sB + it * rstep + k0);
        }
        cp_commit();
    };

    const int nchunk = K / GBK;          // 32
    load_chunk(0, 0);
    load_chunk(1, 1);

    for (int i = 0; i < nchunk; ++i) {
        const int st = i % 3;
        if (i + 2 < nchunk) {
            load_chunk(i + 2, (i + 2) % 3);
            cp_wait2();
        } else if (i + 1 < nchunk) {
            cp_wait1();
        } else {
            cp_wait0();
        }
        __syncthreads();

        const uint32_t sb = smbase + st * STAGE;

#pragma unroll
        for (int ks = 0; ks < 4; ++ks) {
            const uint32_t kd = ks * 32;
            uint32_t ah[2][4], bfr[8][2];
#pragma unroll
            for (int mt = 0; mt < 2; ++mt)
                LDMX4(ah[mt][0], ah[mt][1], ah[mt][2], ah[mt][3],
                      sb + ((aRaw[mt] + kd) ^ aXor[mt]));
#pragma unroll
            for (int g = 0; g < 4; ++g)
                LDMX4(bfr[2 * g][0], bfr[2 * g][1], bfr[2 * g + 1][0], bfr[2 * g + 1][1],
                      sb + B_OFF + ((bRaw[g] + kd) ^ bXor[g]));
#pragma unroll
            for (int mt = 0; mt < 2; ++mt)
#pragma unroll
                for (int nt = 0; nt < 8; ++nt)
                    mma_f16(acc[mt][nt], ah[mt], bfr[nt][0], bfr[nt][1]);
        }
        __syncthreads();
    }
}

// ---- fused QKV projection: B rows = stacked [Wq; Wk; Wv], single pass ----
__global__ __launch_bounds__(256, 2)
void gemm_qkv(const __half* __restrict__ Xh, const __half* __restrict__ W,
              __half* __restrict__ Qh, __half* __restrict__ Kh,
              __half* __restrict__ Vh, float qscale)
{
    extern __shared__ __align__(1024) char dsm[];
    const int bm0 = blockIdx.y * 128;
    const int bn0 = blockIdx.x * 128;
    const int j = bn0 >> 11;             // 0=Q 1=K 2=V

    float acc[2][8][4];
#pragma unroll
    for (int a = 0; a < 2; ++a)
#pragma unroll
        for (int b = 0; b < 8; ++b)
#pragma unroll
            for (int c = 0; c < 4; ++c) acc[a][b][c] = 0.0f;

    gemm_core(Xh, W, bm0, bn0, DMODEL, dsm, acc);

    const int ncol0 = bn0 & 2047;
    __half* dst = (j == 0) ? Qh : (j == 1) ? Kh : Vh;
    const float sc = (j == 0) ? qscale : 1.0f;
    const int wid = (int)threadIdx.x >> 5;
    const int lid = (int)threadIdx.x & 31;
    const int wr = wid >> 1, wc = wid & 1;

#pragma unroll
    for (int mt = 0; mt < 2; ++mt) {
        int row0 = bm0 + wr * 32 + mt * 16 + (lid >> 2);
#pragma unroll
        for (int nt = 0; nt < 8; ++nt) {
            int col = ncol0 + wc * 64 + nt * 8 + (lid & 3) * 2;
            __half h0 = __float2half_rn(acc[mt][nt][0] * sc);
            __half h1 = __float2half_rn(acc[mt][nt][1] * sc);
            __half h2 = __float2half_rn(acc[mt][nt][2] * sc);
            __half h3 = __float2half_rn(acc[mt][nt][3] * sc);
            *(uint32_t*)(dst + (size_t)row0 * DMODEL + col)       = pack_h2(h0, h1);
            *(uint32_t*)(dst + (size_t)(row0 + 8) * DMODEL + col) = pack_h2(h2, h3);
        }
    }
}

// ---- output projection: single-pass fp16 ctx, fp32 out + bias ----
__global__ __launch_bounds__(256, 2)
void gemm_out(const __half* __restrict__ A, const __half* __restrict__ W,
              float* __restrict__ C, const float* __restrict__ bias)
{
    extern __shared__ __align__(1024) char dsm[];
    const int bm0 = blockIdx.y * 128;
    const int bn0 = blockIdx.x * 128;

    float acc[2][8][4];
#pragma unroll
    for (int a = 0; a < 2; ++a)
#pragma unroll
        for (int b = 0; b < 8; ++b)
#pragma unroll
            for (int c = 0; c < 4; ++c) acc[a][b][c] = 0.0f;

    gemm_core(A, W, bm0, bn0, DMODEL, dsm, acc);

    const int wid = (int)threadIdx.x >> 5;
    const int lid = (int)threadIdx.x & 31;
    const int wr = wid >> 1, wc = wid & 1;

#pragma unroll
    for (int mt = 0; mt < 2; ++mt) {
        int row0 = bm0 + wr * 32 + mt * 16 + (lid >> 2);
#pragma unroll
        for (int nt = 0; nt < 8; ++nt) {
            int col = bn0 + wc * 64 + nt * 8 + (lid & 3) * 2;
            float bx = bias[col], by = bias[col + 1];
            float2 v0, v1;
            v0.x = acc[mt][nt][0] + bx; v0.y = acc[mt][nt][1] + by;
            v1.x = acc[mt][nt][2] + bx; v1.y = acc[mt][nt][3] + by;
            *(float2*)(C + (size_t)row0 * DMODEL + col)       = v0;
            *(float2*)(C + (size_t)(row0 + 8) * DMODEL + col) = v1;
        }
    }
}

// ====================== HMMA flash attention (fp16) ========================
// Q single fp16 (32KB), K/V double-buffered (2 x 32KB).
// qt REVERSED (heavy tiles scheduled first); PV single-pass fp16 P.
#define FA_SM_Q  0
#define FA_SM_ST 32768
#define FA_STAGE 32768            // K 16KB + V 16KB
#define FA_SMEM  98304

__global__ __launch_bounds__(256)
void flash_hmma(const __half* __restrict__ Qh, const __half* __restrict__ Kh,
                const __half* __restrict__ Vh, __half* __restrict__ Chi)
{
    extern __shared__ __align__(1024) char dsm[];
    const uint32_t smbase = smem_u32(dsm);

    const int tid = threadIdx.x;
    const int w   = tid >> 5;
    const int lid = tid & 31;

    const int qt = (int)gridDim.x - 1 - (int)blockIdx.x;   // heavy first
    const int h  = blockIdx.y;
    const int bb = blockIdx.z;
    const int tQ = qt * 128;
    const int hc = h * HDIM;
    const int nkt = 2 * qt + 2;

    // ---- hoisted loader constants ----
    const int lrow  = tid >> 4;
    const int ls16  = tid & 15;
    const int lchnk = ls16 >> 3;
    const int lwi   = ls16 & 7;
    const uint32_t lsw =
        (uint32_t)((lrow * 128 + lwi * 16) ^ ((lrow << 4) & 0x70));
    const size_t lsrc0 =
        ((size_t)(bb * SEQ + lrow)) * DMODEL + hc + lchnk * 64 + lwi * 8;
    const size_t lstep = (size_t)16 * DMODEL;

    auto load_Q = [&]() {
        const __half* sQ = Qh + lsrc0 + (size_t)tQ * DMODEL;
        const uint32_t dq = smbase + FA_SM_Q + lchnk * 16384 + lsw;
#pragma unroll
        for (int it = 0; it < 8; ++it)
            cp_async16(dq + it * 2048, sQ + it * lstep);
    };
    auto load_KV = [&](int kt2, int st) {
        const size_t koff = lsrc0 + (size_t)(kt2 * 64) * DMODEL;
        const uint32_t dk = smbase + FA_SM_ST + st * FA_STAGE
                            + lchnk * 8192 + lsw;
        const uint32_t dv = dk + 16384;
        const __half* sK = Kh + koff;
        const __half* sV = Vh + koff;
#pragma unroll
        for (int it = 0; it < 4; ++it) {
            cp_async16(dk + it * 2048, sK + it * lstep);
            cp_async16(dv + it * 2048, sV + it * lstep);
        }
    };

    const uint32_t swXor = (uint32_t)((lid & 7) << 4);
    const uint32_t aRow  = (uint32_t)((w * 16 + (lid & 15)) * 128);
    const uint32_t aCol  = (lid & 16) ? 16u : 0u;
    uint32_t bRow[4];
#pragma unroll
    for (int g = 0; g < 4; ++g)
        bRow[g] = (uint32_t)((g * 16 + (lid & 7) + ((lid & 16) ? 8 : 0)) * 128);
    const uint32_t bCol  = (lid & 8) ? 16u : 0u;
    const uint32_t vRow  = (uint32_t)((lid & 15) * 128);
    const uint32_t vCol  = (lid & 16) ? 16u : 0u;

    float cacc[16][4];
#pragma unroll
    for (int i = 0; i < 16; ++i)
#pragma unroll
        for (int j = 0; j < 4; ++j) cacc[i][j] = 0.0f;
    float mrun[2] = {-1e30f, -1e30f};
    float lsum[2] = {0.0f, 0.0f};

    const int wrow = qt * 128 + w * 16;

    load_Q();
    load_KV(0, 0);
    cp_commit();

    for (int kt = 0; kt < nkt; ++kt) {
        const int s = kt & 1;
        __syncthreads();
        if (kt + 1 < nkt) { load_KV(kt + 1, s ^ 1); cp_commit(); cp_wait1(); }
        else              { cp_wait0(); }
        __syncthreads();

        const bool skip = (kt * 64 > wrow + 15);
        if (skip) continue;

        const uint32_t sK = smbase + FA_SM_ST + s * FA_STAGE;
        const uint32_t sV = sK + 16384;

        // ---- S = Q K^T (single pass) ----
        float sacc[8][4];
#pragma unroll
        for (int i = 0; i < 8; ++i)
#pragma unroll
            for (int j = 0; j < 4; ++j) sacc[i][j] = 0.0f;

#pragma unroll
        for (int t = 0; t < 8; ++t) {
            const uint32_t cb  = (uint32_t)((t & 3) * 32);
            const uint32_t qch = (uint32_t)((t >> 2) * 16384);
            const uint32_t kch = (uint32_t)((t >> 2) * 8192);
            uint32_t qf[4], kb[4][4];
            LDMX4(qf[0], qf[1], qf[2], qf[3],
                  smbase + FA_SM_Q + qch + aRow + ((cb + aCol) ^ swXor));
#pragma unroll
            for (int g = 0; g < 4; ++g)
                LDMX4(kb[g][0], kb[g][1], kb[g][2], kb[g][3],
                      sK + kch + bRow[g] + ((cb + bCol) ^ swXor));
#pragma unroll
            for (int g = 0; g < 4; ++g) {
                mma_f16(sacc[2 * g],     qf, kb[g][0], kb[g][1]);
                mma_f16(sacc[2 * g + 1], qf, kb[g][2], kb[g][3]);
            }
        }

        // ---- online softmax (exp2 domain) ----
        const bool need_mask = (kt * 64 + 63 > wrow);
#pragma unroll
        for (int i = 0; i < 2; ++i) {
            const int qr = wrow + (lid >> 2) + 8 * i;
            if (need_mask) {
#pragma unroll
                for (int nt = 0; nt < 8; ++nt) {
                    int c0 = kt * 64 + nt * 8 + (lid & 3) * 2;
                    if (c0     > qr) sacc[nt][2 * i]     = -1e30f;
                    if (c0 + 1 > qr) sacc[nt][2 * i + 1] = -1e30f;
                }
            }
            float mx = -1e30f;
#pragma unroll
            for (int nt = 0; nt < 8; ++nt)
                mx = fmaxf(mx, fmaxf(sacc[nt][2 * i], sacc[nt][2 * i + 1]));
            mx = fmaxf(mx, __shfl_xor_sync(0xffffffffu, mx, 1));
            mx = fmaxf(mx, __shfl_xor_sync(0xffffffffu, mx, 2));

            float mnew  = fmaxf(mrun[i], mx);
            float alpha = ex2(mrun[i] - mnew);
            float rs = 0.0f;
#pragma unroll
            for (int nt = 0; nt < 8; ++nt) {
                float p0 = ex2(sacc[nt][2 * i]     - mnew);
                float p1 = ex2(sacc[nt][2 * i + 1] - mnew);
                sacc[nt][2 * i] = p0; sacc[nt][2 * i + 1] = p1;
                rs += p0 + p1;
            }
            rs += __shfl_xor_sync(0xffffffffu, rs, 1);
            rs += __shfl_xor_sync(0xffffffffu, rs, 2);
            lsum[i] = lsum[i] * alpha + rs;
            mrun[i] = mnew;
#pragma unroll
            for (int nt = 0; nt < 16; ++nt) {
                cacc[nt][2 * i]     *= alpha;
                cacc[nt][2 * i + 1] *= alpha;
            }
        }

        // ---- O += P V (single-pass fp16 P) ----
#pragma unroll
        for (int t = 0; t < 4; ++t) {
            uint32_t pf[4];
#pragma unroll
            for (int u = 0; u < 4; ++u) {
                int tile = 2 * t + (u >> 1);
                int r0   = (u & 1) * 2;
                pf[u] = pack_h2(__float2half_rn(sacc[tile][r0]),
                                __float2half_rn(sacc[tile][r0 + 1]));
            }
            const uint32_t vt = (uint32_t)(t * 2048);
#pragma unroll
            for (int j = 0; j < 8; ++j) {
                const uint32_t cb = (uint32_t)((j & 3) * 32) + vCol;
                uint32_t b0, b1, b2, b3;
                LDMX4T(b0, b1, b2, b3,
                       sV + (uint32_t)((j >> 2) * 8192) + vRow + vt + (cb ^ swXor));
                mma_f16(cacc[2 * j],     pf, b0, b1);
                mma_f16(cacc[2 * j + 1], pf, b2, b3);
            }
        }
    }

    // epilogue: normalize + fp16 ctx store
#pragma unroll
    for (int i = 0; i < 2; ++i) {
        float inv = 1.0f / lsum[i];
        int row = tQ + w * 16 + (lid >> 2) + 8 * i;
        size_t gbase = ((size_t)(bb * SEQ + row)) * DMODEL + hc;
#pragma unroll
        for (int nt = 0; nt < 16; ++nt) {
            int col = nt * 8 + (lid & 3) * 2;
            float v0 = cacc[nt][2 * i]     * inv;
            float v1 = cacc[nt][2 * i + 1] * inv;
            *(uint32_t*)(Chi + gbase + col) =
                pack_h2(__float2half_rn(v0), __float2half_rn(v1));
        }
    }
}

// ---------------------------------------------------------------------------
extern "C" void kernel_launch(void* const* d_in, const int* in_sizes, int n_in,
                              void* d_out, int out_size)
{
    (void)in_sizes; (void)n_in; (void)out_size;
    const float* x  = (const float*)d_in[0];
    const float* Wq = (const float*)d_in[1];
    const float* Wk = (const float*)d_in[2];
    const float* Wv = (const float*)d_in[3];
    const float* Wo = (const float*)d_in[4];
    const float* bo = (const float*)d_in[5];
    float* out = (float*)d_out;

    __half *qh, *kh, *vh, *xh, *chi, *wh;
    cudaGetSymbolAddress((void**)&qh, g_qh);
    cudaGetSymbolAddress((void**)&kh, g_kh);
    cudaGetSymbolAddress((void**)&vh, g_vh);
    cudaGetSymbolAddress((void**)&xh, g_xh);
    cudaGetSymbolAddress((void**)&chi, g_chi);
    cudaGetSymbolAddress((void**)&wh, g_wh);

    const size_t WN = (size_t)DMODEL * DMODEL;
    const float qscale = 0.08838834764831845f * 1.4426950408889634f;

    cudaFuncSetAttribute(gemm_qkv,
                         cudaFuncAttributeMaxDynamicSharedMemorySize, GEMM_SMEM);
    cudaFuncSetAttribute(gemm_out,
                         cudaFuncAttributeMaxDynamicSharedMemorySize, GEMM_SMEM);
    cudaFuncSetAttribute(flash_hmma,
                         cudaFuncAttributeMaxDynamicSharedMemorySize, FA_SMEM);

    // 1) fused convert: x and weights -> fp16 (coalesced, 4 float4/thread)
    int ntot = NX4 + 4 * NW4;
    split_all<<<ntot / 1024, 256>>>((const float4*)x,
        (const float4*)Wq, (const float4*)Wk, (const float4*)Wv, (const float4*)Wo,
        (__half2*)xh, (__half2*)wh);

    // 2) fused QKV projection (single pass)
    dim3 qkvgrid(3 * DMODEL / 128, M_TOK / 128);    // (48, 64)
    gemm_qkv<<<qkvgrid, 256, GEMM_SMEM>>>(xh, wh, qh, kh, vh, qscale);

    // 3) flash attention (heavy-tiles-first, PV single-pass) -> fp16 ctx
    dim3 fgrid(SEQ / 128, NHEADS, BATCH);
    flash_hmma<<<fgrid, 256, FA_SMEM>>>(qh, kh, vh, chi);

    // 4) output projection + bias (single pass, fp32 out)
    dim3 ogrid(DMODEL / 128, M_TOK / 128);          // (16, 64)
    gemm_out<<<ogrid, 256, GEMM_SMEM>>>(chi, wh + 3 * WN, out, bo);
}